// round 14
// baseline (speedup 1.0000x reference)
#include <cuda_runtime.h>
#include <math.h>

#define NN 100000
#define EE 3200000
#define IN_F 256
#define ATT_D 128
#define SLOPE 0.2f

// ---------------- device scratch (no runtime allocation allowed) ----------
__device__ float g_wsrc[IN_F];
__device__ float g_wdst[IN_F];
__device__ float g_ssrc[NN];
__device__ float g_sdst[NN];
__device__ float g_denom[NN];
__device__ int   g_is64;     // 1 if edge buffer is int64, 0 if int32

// ---------------- pre: wvec (warp-per-row) | zero denom | sniff -------------
#define WVEC_BLOCKS 32
__global__ void k_pre(const float* __restrict__ W, const float* __restrict__ a,
                      const long long* __restrict__ edge, int n, int ZB) {
    int b = blockIdx.x;
    if (b < WVEC_BLOCKS) {
        int w    = threadIdx.x >> 5;
        int lane = threadIdx.x & 31;
        int t    = b * 8 + w;                       // output row 0..255
        const float4* row = reinterpret_cast<const float4*>(W + (size_t)t * ATT_D);
        float4 wv = __ldg(&row[lane]);
        float4 as = __ldg(&reinterpret_cast<const float4*>(a)[lane]);        // a[:128]
        float4 ad = __ldg(&reinterpret_cast<const float4*>(a)[32 + lane]);   // a[128:]
        float ws = wv.x * as.x + wv.y * as.y + wv.z * as.z + wv.w * as.w;
        float wd = wv.x * ad.x + wv.y * ad.y + wv.z * ad.z + wv.w * ad.w;
#pragma unroll
        for (int off = 16; off; off >>= 1) {
            ws += __shfl_xor_sync(0xffffffffu, ws, off);
            wd += __shfl_xor_sync(0xffffffffu, wd, off);
        }
        if (lane == 0) {
            g_wsrc[t] = ws;
            g_wdst[t] = wd;
        }
    } else if (b < WVEC_BLOCKS + ZB) {
        int i = ((b - WVEC_BLOCKS) * blockDim.x + threadIdx.x) << 2;
        if (i + 3 < n) {
            *reinterpret_cast<float4*>(g_denom + i) = make_float4(0.f, 0.f, 0.f, 0.f);
        } else {
            for (int k = 0; k < 4 && i + k < n; ++k) g_denom[i + k] = 0.f;
        }
    } else {
        if (threadIdx.x == 0) {
            int is64 = 1;
            for (int i = 0; i < 256; ++i) {
                long long v = edge[i];
                if (v < 0 || v >= (long long)n) { is64 = 0; break; }
            }
            g_is64 = is64;
        }
    }
}

// ---------------- node scores: 2 rows per warp (proven R13) -----------------
__global__ void k_node_scores(const float* __restrict__ x, int n) {
    int gw   = (blockIdx.x * blockDim.x + threadIdx.x) >> 5;
    int lane = threadIdx.x & 31;
    int r0 = gw * 2, r1 = r0 + 1;
    if (r0 >= n) return;
    bool has1 = (r1 < n);
    const float4* x0 = reinterpret_cast<const float4*>(x + (size_t)r0 * IN_F);
    const float4* x1 = reinterpret_cast<const float4*>(x + (size_t)(has1 ? r1 : r0) * IN_F);
    const float4* ws = reinterpret_cast<const float4*>(g_wsrc);
    const float4* wd = reinterpret_cast<const float4*>(g_wdst);
    float a00 = 0.f, a01 = 0.f, a10 = 0.f, a11 = 0.f;
#pragma unroll
    for (int k = 0; k < IN_F / 4 / 32; ++k) {   // 2 iters
        float4 v0 = x0[lane + 32 * k];
        float4 v1 = x1[lane + 32 * k];
        float4 sv = __ldg(&ws[lane + 32 * k]);
        float4 dv = __ldg(&wd[lane + 32 * k]);
        a00 += v0.x * sv.x + v0.y * sv.y + v0.z * sv.z + v0.w * sv.w;
        a01 += v0.x * dv.x + v0.y * dv.y + v0.z * dv.z + v0.w * dv.w;
        a10 += v1.x * sv.x + v1.y * sv.y + v1.z * sv.z + v1.w * sv.w;
        a11 += v1.x * dv.x + v1.y * dv.y + v1.z * dv.z + v1.w * dv.w;
    }
#pragma unroll
    for (int off = 16; off; off >>= 1) {
        a00 += __shfl_xor_sync(0xffffffffu, a00, off);
        a01 += __shfl_xor_sync(0xffffffffu, a01, off);
        a10 += __shfl_xor_sync(0xffffffffu, a10, off);
        a11 += __shfl_xor_sync(0xffffffffu, a11, off);
    }
    if (lane == 0) {
        g_ssrc[r0] = a00;
        g_sdst[r0] = a01;
        if (has1) { g_ssrc[r1] = a10; g_sdst[r1] = a11; }
    }
}

// ---------------- edge pass 1 (R11/R13, proven — UNCHANGED) -----------------
__global__ void k_edgeB(const void* __restrict__ edge_raw,
                        float* __restrict__ out, int e_cnt, int n) {
    int i = (blockIdx.x * blockDim.x + threadIdx.x) << 2;
    if (i >= e_cnt) return;
    const unsigned nm1 = (unsigned)(n - 1);
    int src[4], dst[4];
    bool full = (i + 3 < e_cnt);
    if (g_is64) {
        const long long* ep = (const long long*)edge_raw;
        if (full) {
            longlong2 s0 = *(const longlong2*)(ep + i);
            longlong2 s1 = *(const longlong2*)(ep + i + 2);
            longlong2 d0 = *(const longlong2*)(ep + (size_t)e_cnt + i);
            longlong2 d1 = *(const longlong2*)(ep + (size_t)e_cnt + i + 2);
            src[0] = (int)s0.x; src[1] = (int)s0.y; src[2] = (int)s1.x; src[3] = (int)s1.y;
            dst[0] = (int)d0.x; dst[1] = (int)d0.y; dst[2] = (int)d1.x; dst[3] = (int)d1.y;
        } else {
            for (int k = 0; k < 4; ++k) {
                int e = min(i + k, e_cnt - 1);
                src[k] = (int)ep[e];
                dst[k] = (int)ep[(size_t)e_cnt + e];
            }
        }
    } else {
        const int* ep = (const int*)edge_raw;
        if (full) {
            int4 s = *(const int4*)(ep + i);
            int4 d = *(const int4*)(ep + (size_t)e_cnt + i);
            src[0] = s.x; src[1] = s.y; src[2] = s.z; src[3] = s.w;
            dst[0] = d.x; dst[1] = d.y; dst[2] = d.z; dst[3] = d.w;
        } else {
            for (int k = 0; k < 4; ++k) {
                int e = min(i + k, e_cnt - 1);
                src[k] = ep[e];
                dst[k] = ep[(size_t)e_cnt + e];
            }
        }
    }
    float ex[4];
#pragma unroll
    for (int k = 0; k < 4; ++k) {
        unsigned ss = min((unsigned)src[k], nm1);
        unsigned dd = min((unsigned)dst[k], nm1);
        src[k] = (int)ss;
        float s = g_ssrc[ss] + g_sdst[dd];
        s = (s >= 0.f) ? s : SLOPE * s;
        ex[k] = __expf(s);
    }
    if (full) {
        *reinterpret_cast<float4*>(out + i) = make_float4(ex[0], ex[1], ex[2], ex[3]);
#pragma unroll
        for (int k = 0; k < 4; ++k) atomicAdd(&g_denom[src[k]], ex[k]);
    } else {
        for (int k = 0; k < 4 && i + k < e_cnt; ++k) {
            out[i + k] = ex[k];
            atomicAdd(&g_denom[src[k]], ex[k]);
        }
    }
}

// ---------------- edge pass 2: normalize, 8 edges/thread --------------------
// edgeC is latency-exposed (issue 11%): front-batch 2x int4 + 2x float4 + 8
// gathers per thread to cover the dependent-load chain. Lean body (no dst,
// no exp) so no spill risk, unlike the failed 8x edgeB.
__global__ void __launch_bounds__(256) k_edgeC(const void* __restrict__ edge_raw,
                                               float* __restrict__ out,
                                               int e_cnt, int n) {
    int i = (blockIdx.x * blockDim.x + threadIdx.x) << 3;
    if (i >= e_cnt) return;
    const unsigned nm1 = (unsigned)(n - 1);
    if (!g_is64 && i + 7 < e_cnt) {
        const int* ep = (const int*)edge_raw;
        int4 s0 = __ldg((const int4*)(ep + i));
        int4 s1 = __ldg((const int4*)(ep + i + 4));
        float4 v0 = *reinterpret_cast<const float4*>(out + i);
        float4 v1 = *reinterpret_cast<const float4*>(out + i + 4);
        float d0 = g_denom[min((unsigned)s0.x, nm1)];
        float d1 = g_denom[min((unsigned)s0.y, nm1)];
        float d2 = g_denom[min((unsigned)s0.z, nm1)];
        float d3 = g_denom[min((unsigned)s0.w, nm1)];
        float d4 = g_denom[min((unsigned)s1.x, nm1)];
        float d5 = g_denom[min((unsigned)s1.y, nm1)];
        float d6 = g_denom[min((unsigned)s1.z, nm1)];
        float d7 = g_denom[min((unsigned)s1.w, nm1)];
        v0.x = __fdividef(v0.x, d0 + 1e-16f);
        v0.y = __fdividef(v0.y, d1 + 1e-16f);
        v0.z = __fdividef(v0.z, d2 + 1e-16f);
        v0.w = __fdividef(v0.w, d3 + 1e-16f);
        v1.x = __fdividef(v1.x, d4 + 1e-16f);
        v1.y = __fdividef(v1.y, d5 + 1e-16f);
        v1.z = __fdividef(v1.z, d6 + 1e-16f);
        v1.w = __fdividef(v1.w, d7 + 1e-16f);
        *reinterpret_cast<float4*>(out + i)     = v0;
        *reinterpret_cast<float4*>(out + i + 4) = v1;
    } else {
        const int is64 = g_is64;
        for (int k = 0; k < 8; ++k) {
            int e = i + k;
            if (e >= e_cnt) break;
            int src;
            if (is64) src = (int)((const long long*)edge_raw)[e];
            else      src = ((const int*)edge_raw)[e];
            out[e] = __fdividef(out[e], g_denom[min((unsigned)src, nm1)] + 1e-16f);
        }
    }
}

// ---------------- launch ------------------------------------------------------
extern "C" void kernel_launch(void* const* d_in, const int* in_sizes, int n_in,
                              void* d_out, int out_size) {
    const float* x    = (const float*)d_in[0];   // [N, 256] f32
    const void*  edge = d_in[1];                  // [2, E] int32 or int64
    const float* W    = (const float*)d_in[2];   // [256, 128] f32
    const float* a    = (const float*)d_in[3];   // [256] f32
    float* out = (float*)d_out;                   // [E, 1] f32

    const int n = in_sizes[0] / IN_F;   // 100000
    const int e = out_size;             // 3200000

    const int ZB = (n / 4 + 255) / 256;                 // denom-zero blocks
    k_pre<<<WVEC_BLOCKS + ZB + 1, 256>>>(W, a, (const long long*)edge, n, ZB);
    k_node_scores<<<(n + 15) / 16, 256>>>(x, n);        // 2 rows per warp
    const int eb = (e / 4 + 255) / 256;
    k_edgeB<<<eb, 256>>>(edge, out, e, n);
    const int ec = (e / 8 + 255) / 256;
    k_edgeC<<<ec, 256>>>(edge, out, e, n);
}

// round 16
// speedup vs baseline: 1.0331x; 1.0331x over previous
#include <cuda_runtime.h>
#include <math.h>

#define NN 100000
#define EE 3200000
#define IN_F 256
#define ATT_D 128
#define SLOPE 0.2f

// ---------------- device scratch (no runtime allocation allowed) ----------
__device__ float g_wsrc[IN_F];
__device__ float g_wdst[IN_F];
__device__ float g_ssrc[NN];
__device__ float g_sdst[NN];
__device__ float g_denom[NN];
__device__ int   g_is64;     // 1 if edge buffer is int64, 0 if int32

// ---------------- pre: wvec (warp-per-row) | zero denom | sniff -------------
// blocks [0,32): wvec, warp-per-output-row, one coalesced load wave.
// blocks [32, 32+ZB): zero denom, float4.
// block  32+ZB: warp-parallel dtype sniff (32 probes + ballot, 1 load wave).
#define WVEC_BLOCKS 32
__global__ void k_pre(const float* __restrict__ W, const float* __restrict__ a,
                      const long long* __restrict__ edge, int n, int ZB) {
    int b = blockIdx.x;
    if (b < WVEC_BLOCKS) {
        int w    = threadIdx.x >> 5;
        int lane = threadIdx.x & 31;
        int t    = b * 8 + w;                       // output row 0..255
        const float4* row = reinterpret_cast<const float4*>(W + (size_t)t * ATT_D);
        float4 wv = __ldg(&row[lane]);
        float4 as = __ldg(&reinterpret_cast<const float4*>(a)[lane]);        // a[:128]
        float4 ad = __ldg(&reinterpret_cast<const float4*>(a)[32 + lane]);   // a[128:]
        float ws = wv.x * as.x + wv.y * as.y + wv.z * as.z + wv.w * as.w;
        float wd = wv.x * ad.x + wv.y * ad.y + wv.z * ad.z + wv.w * ad.w;
#pragma unroll
        for (int off = 16; off; off >>= 1) {
            ws += __shfl_xor_sync(0xffffffffu, ws, off);
            wd += __shfl_xor_sync(0xffffffffu, wd, off);
        }
        if (lane == 0) {
            g_wsrc[t] = ws;
            g_wdst[t] = wd;
        }
    } else if (b < WVEC_BLOCKS + ZB) {
        int i = ((b - WVEC_BLOCKS) * blockDim.x + threadIdx.x) << 2;
        if (i + 3 < n) {
            *reinterpret_cast<float4*>(g_denom + i) = make_float4(0.f, 0.f, 0.f, 0.f);
        } else {
            for (int k = 0; k < 4 && i + k < n; ++k) g_denom[i + k] = 0.f;
        }
    } else {
        // warp-parallel dtype sniff: 32 independent probes, one load wave.
        // int32 data read as int64 is out of [0,n) unless the paired hi-word
        // is 0 (P ~ 1e-5 per probe) -> P(misdetect) ~ 1e-160.
        if (threadIdx.x < 32) {
            long long v = edge[threadIdx.x];
            bool bad = (v < 0 || v >= (long long)n);
            unsigned m = __ballot_sync(0xffffffffu, bad);
            if (threadIdx.x == 0) g_is64 = (m == 0u) ? 1 : 0;
        }
    }
}

// ---------------- node scores: 2 rows per warp (proven R13) -----------------
__global__ void k_node_scores(const float* __restrict__ x, int n) {
    int gw   = (blockIdx.x * blockDim.x + threadIdx.x) >> 5;
    int lane = threadIdx.x & 31;
    int r0 = gw * 2, r1 = r0 + 1;
    if (r0 >= n) return;
    bool has1 = (r1 < n);
    const float4* x0 = reinterpret_cast<const float4*>(x + (size_t)r0 * IN_F);
    const float4* x1 = reinterpret_cast<const float4*>(x + (size_t)(has1 ? r1 : r0) * IN_F);
    const float4* ws = reinterpret_cast<const float4*>(g_wsrc);
    const float4* wd = reinterpret_cast<const float4*>(g_wdst);
    float a00 = 0.f, a01 = 0.f, a10 = 0.f, a11 = 0.f;
#pragma unroll
    for (int k = 0; k < IN_F / 4 / 32; ++k) {   // 2 iters
        float4 v0 = x0[lane + 32 * k];
        float4 v1 = x1[lane + 32 * k];
        float4 sv = __ldg(&ws[lane + 32 * k]);
        float4 dv = __ldg(&wd[lane + 32 * k]);
        a00 += v0.x * sv.x + v0.y * sv.y + v0.z * sv.z + v0.w * sv.w;
        a01 += v0.x * dv.x + v0.y * dv.y + v0.z * dv.z + v0.w * dv.w;
        a10 += v1.x * sv.x + v1.y * sv.y + v1.z * sv.z + v1.w * sv.w;
        a11 += v1.x * dv.x + v1.y * dv.y + v1.z * dv.z + v1.w * dv.w;
    }
#pragma unroll
    for (int off = 16; off; off >>= 1) {
        a00 += __shfl_xor_sync(0xffffffffu, a00, off);
        a01 += __shfl_xor_sync(0xffffffffu, a01, off);
        a10 += __shfl_xor_sync(0xffffffffu, a10, off);
        a11 += __shfl_xor_sync(0xffffffffu, a11, off);
    }
    if (lane == 0) {
        g_ssrc[r0] = a00;
        g_sdst[r0] = a01;
        if (has1) { g_ssrc[r1] = a10; g_sdst[r1] = a11; }
    }
}

// ---------------- edge pass 1 (R11/R13, proven — UNCHANGED) -----------------
__global__ void k_edgeB(const void* __restrict__ edge_raw,
                        float* __restrict__ out, int e_cnt, int n) {
    int i = (blockIdx.x * blockDim.x + threadIdx.x) << 2;
    if (i >= e_cnt) return;
    const unsigned nm1 = (unsigned)(n - 1);
    int src[4], dst[4];
    bool full = (i + 3 < e_cnt);
    if (g_is64) {
        const long long* ep = (const long long*)edge_raw;
        if (full) {
            longlong2 s0 = *(const longlong2*)(ep + i);
            longlong2 s1 = *(const longlong2*)(ep + i + 2);
            longlong2 d0 = *(const longlong2*)(ep + (size_t)e_cnt + i);
            longlong2 d1 = *(const longlong2*)(ep + (size_t)e_cnt + i + 2);
            src[0] = (int)s0.x; src[1] = (int)s0.y; src[2] = (int)s1.x; src[3] = (int)s1.y;
            dst[0] = (int)d0.x; dst[1] = (int)d0.y; dst[2] = (int)d1.x; dst[3] = (int)d1.y;
        } else {
            for (int k = 0; k < 4; ++k) {
                int e = min(i + k, e_cnt - 1);
                src[k] = (int)ep[e];
                dst[k] = (int)ep[(size_t)e_cnt + e];
            }
        }
    } else {
        const int* ep = (const int*)edge_raw;
        if (full) {
            int4 s = *(const int4*)(ep + i);
            int4 d = *(const int4*)(ep + (size_t)e_cnt + i);
            src[0] = s.x; src[1] = s.y; src[2] = s.z; src[3] = s.w;
            dst[0] = d.x; dst[1] = d.y; dst[2] = d.z; dst[3] = d.w;
        } else {
            for (int k = 0; k < 4; ++k) {
                int e = min(i + k, e_cnt - 1);
                src[k] = ep[e];
                dst[k] = ep[(size_t)e_cnt + e];
            }
        }
    }
    float ex[4];
#pragma unroll
    for (int k = 0; k < 4; ++k) {
        unsigned ss = min((unsigned)src[k], nm1);   // clamp: safety, no-op normally
        unsigned dd = min((unsigned)dst[k], nm1);
        src[k] = (int)ss;
        float s = g_ssrc[ss] + g_sdst[dd];
        s = (s >= 0.f) ? s : SLOPE * s;
        ex[k] = __expf(s);
    }
    if (full) {
        *reinterpret_cast<float4*>(out + i) = make_float4(ex[0], ex[1], ex[2], ex[3]);
#pragma unroll
        for (int k = 0; k < 4; ++k) atomicAdd(&g_denom[src[k]], ex[k]);
    } else {
        for (int k = 0; k < 4 && i + k < e_cnt; ++k) {
            out[i + k] = ex[k];
            atomicAdd(&g_denom[src[k]], ex[k]);
        }
    }
}

// ---------------- edge pass 2 (R13 body; final stores streamed) -------------
__global__ void k_edgeC(const void* __restrict__ edge_raw,
                        float* __restrict__ out, int e_cnt, int n) {
    int i = (blockIdx.x * blockDim.x + threadIdx.x) << 2;
    if (i >= e_cnt) return;
    const unsigned nm1 = (unsigned)(n - 1);
    int src[4];
    bool full = (i + 3 < e_cnt);
    if (g_is64) {
        const long long* ep = (const long long*)edge_raw;
        if (full) {
            longlong2 s0 = *(const longlong2*)(ep + i);
            longlong2 s1 = *(const longlong2*)(ep + i + 2);
            src[0] = (int)s0.x; src[1] = (int)s0.y; src[2] = (int)s1.x; src[3] = (int)s1.y;
        } else {
            for (int k = 0; k < 4; ++k) src[k] = (int)ep[min(i + k, e_cnt - 1)];
        }
    } else {
        const int* ep = (const int*)edge_raw;
        if (full) {
            int4 s = *(const int4*)(ep + i);
            src[0] = s.x; src[1] = s.y; src[2] = s.z; src[3] = s.w;
        } else {
            for (int k = 0; k < 4; ++k) src[k] = ep[min(i + k, e_cnt - 1)];
        }
    }
    if (full) {
        float4 v = *reinterpret_cast<const float4*>(out + i);
        v.x = __fdividef(v.x, g_denom[min((unsigned)src[0], nm1)] + 1e-16f);
        v.y = __fdividef(v.y, g_denom[min((unsigned)src[1], nm1)] + 1e-16f);
        v.z = __fdividef(v.z, g_denom[min((unsigned)src[2], nm1)] + 1e-16f);
        v.w = __fdividef(v.w, g_denom[min((unsigned)src[3], nm1)] + 1e-16f);
        __stcs(reinterpret_cast<float4*>(out + i), v);   // evict-first: never re-read
    } else {
        for (int k = 0; k < 4 && i + k < e_cnt; ++k)
            out[i + k] = __fdividef(out[i + k],
                                    g_denom[min((unsigned)src[k], nm1)] + 1e-16f);
    }
}

// ---------------- launch ------------------------------------------------------
extern "C" void kernel_launch(void* const* d_in, const int* in_sizes, int n_in,
                              void* d_out, int out_size) {
    const float* x    = (const float*)d_in[0];   // [N, 256] f32
    const void*  edge = d_in[1];                  // [2, E] int32 or int64
    const float* W    = (const float*)d_in[2];   // [256, 128] f32
    const float* a    = (const float*)d_in[3];   // [256] f32
    float* out = (float*)d_out;                   // [E, 1] f32

    const int n = in_sizes[0] / IN_F;   // 100000
    const int e = out_size;             // 3200000

    const int ZB = (n / 4 + 255) / 256;                 // denom-zero blocks
    k_pre<<<WVEC_BLOCKS + ZB + 1, 256>>>(W, a, (const long long*)edge, n, ZB);
    k_node_scores<<<(n + 15) / 16, 256>>>(x, n);        // 2 rows per warp
    const int eb = (e / 4 + 255) / 256;
    k_edgeB<<<eb, 256>>>(edge, out, e, n);
    k_edgeC<<<eb, 256>>>(edge, out, e, n);
}